// round 16
// baseline (speedup 1.0000x reference)
#include <cuda_runtime.h>
#include <cuda_bf16.h>
#include <math.h>
#include <stdint.h>

#define BATCH 2048
#define DM    256
#define NF    32768
#define KB    8
#define CHUNK 1024
#define MAX_ITEMS 48
#define KPH   36
#define STG   36864u      // bytes per pipeline stage (A 18432 + B 18432)
#define AP    136         // epilogue staging row pitch (bf16 elements)

// ---------------- device globals ----------------
__device__ __nv_bfloat16 g_xn[BATCH * DM];
__device__ float         g_xn32[BATCH * DM];
__device__ __nv_bfloat16 g_acts[(size_t)BATCH * NF];
__device__ __nv_bfloat16 g_WencT[(size_t)NF * DM];
__device__ __nv_bfloat16 g_WdecT[(size_t)DM * NF];
__device__ __nv_bfloat16 g_part[(size_t)MAX_ITEMS * BATCH * DM];
__device__ float g_wdn10[NF];
__device__ float g_cwseg[NF];
__device__ float g_cw[KB];
__device__ float g_normpart[BATCH / 8];
__device__ float g_scale, g_l1sum, g_l0sum;
__device__ float g_errsum[KB];
__device__ int   g_items[4 * MAX_ITEMS];
__device__ int   g_order[MAX_ITEMS];

// ---------------- helpers ----------------
__device__ __forceinline__ void cp16(uint32_t dst, const void* src) {
    asm volatile("cp.async.cg.shared.global [%0], [%1], 16;" :: "r"(dst), "l"(src));
}
#define CP_COMMIT() asm volatile("cp.async.commit_group;" ::: "memory")
#define CP_WAIT1()  asm volatile("cp.async.wait_group 1;" ::: "memory")

__device__ __forceinline__ void mma16(float* c, const uint32_t* a, const uint32_t* b) {
    asm volatile(
        "mma.sync.aligned.m16n8k16.row.col.f32.bf16.bf16.f32 "
        "{%0,%1,%2,%3}, {%4,%5,%6,%7}, {%8,%9}, {%0,%1,%2,%3};"
        : "+f"(c[0]), "+f"(c[1]), "+f"(c[2]), "+f"(c[3])
        : "r"(a[0]), "r"(a[1]), "r"(a[2]), "r"(a[3]), "r"(b[0]), "r"(b[1]));
}

#define LDMX4(r0, r1, r2, r3, addr) \
    asm volatile("ldmatrix.sync.aligned.m8n8.x4.shared.b16 {%0,%1,%2,%3}, [%4];" \
        : "=r"(r0), "=r"(r1), "=r"(r2), "=r"(r3) : "r"(addr))

__device__ __forceinline__ void compute_chunk(uint32_t As, uint32_t Bs,
                                              const uint32_t aOff[2], const uint32_t bOff[4],
                                              float c[2][8][4]) {
    #pragma unroll
    for (int k4 = 0; k4 < 4; k4++) {
        uint32_t kb = (uint32_t)k4 * 32u;
        uint32_t a[2][4];
        LDMX4(a[0][0], a[0][1], a[0][2], a[0][3], As + aOff[0] + kb);
        LDMX4(a[1][0], a[1][1], a[1][2], a[1][3], As + aOff[1] + kb);
        uint32_t bb[4][4];
        #pragma unroll
        for (int nj = 0; nj < 4; nj++)
            LDMX4(bb[nj][0], bb[nj][1], bb[nj][2], bb[nj][3], Bs + bOff[nj] + kb);
        #pragma unroll
        for (int ni = 0; ni < 8; ni++) {
            uint32_t b2[2] = { bb[ni >> 1][(ni & 1) * 2], bb[ni >> 1][(ni & 1) * 2 + 1] };
            mma16(c[0][ni], a[0], b2);
            mma16(c[1][ni], a[1], b2);
        }
    }
}

// ---------------- small kernels ----------------
__global__ void k_norms(const float* __restrict__ x) {
    __shared__ float wsum[8];
    int warp = threadIdx.x >> 5, lane = threadIdx.x & 31;
    int row = blockIdx.x * 8 + warp;
    const float* p = x + row * DM + lane * 8;
    float4 v0 = *(const float4*)p;
    float4 v1 = *(const float4*)(p + 4);
    float s = v0.x*v0.x + v0.y*v0.y + v0.z*v0.z + v0.w*v0.w
            + v1.x*v1.x + v1.y*v1.y + v1.z*v1.z + v1.w*v1.w;
    #pragma unroll
    for (int o = 16; o > 0; o >>= 1) s += __shfl_down_sync(0xffffffffu, s, o);
    if (lane == 0) wsum[warp] = sqrtf(s);
    __syncthreads();
    if (threadIdx.x == 0) {
        float t = 0.f;
        #pragma unroll
        for (int i = 0; i < 8; i++) t += wsum[i];
        g_normpart[blockIdx.x] = t;
    }
}

__global__ void k_prep(const float* __restrict__ ravg, const float* __restrict__ w) {
    __shared__ float red[256];
    int tid = threadIdx.x;
    red[tid] = g_normpart[tid];
    __syncthreads();
    for (int s = 128; s > 0; s >>= 1) {
        if (tid < s) red[tid] += red[tid + s];
        __syncthreads();
    }
    if (tid == 0) {
        float mean = red[0] / (float)BATCH;
        float ra = 0.99f * ravg[0] + 0.01f * mean;
        g_scale = 16.0f / ra;
        float s = 0.0f;
        for (int j = KB - 1; j >= 0; j--) { s += w[j]; g_cw[j] = s / (float)KB; }
        g_l1sum = 0.f; g_l0sum = 0.f;
    }
}

#define BLK_TRE  4096
#define BLK_TRD  1024
#define BLK_XN   (BATCH * DM / 256)
#define ALL_BLOCKS (BLK_TRE + BLK_TRD + BLK_XN + 1)

__global__ void k_all(const float* __restrict__ Wenc, const float* __restrict__ Wdec,
                      const int* __restrict__ seg, const float* __restrict__ x) {
    int b = blockIdx.x;
    int tx = threadIdx.x & 31, ty = threadIdx.x >> 5;
    if (b < BLK_TRE) {
        __shared__ float t[64][33];
        int fx = (b & 1023) * 32;
        int dy = (b >> 10) * 64;
        #pragma unroll
        for (int j = 0; j < 64; j += 8)
            t[ty + j][tx] = Wenc[(size_t)(dy + ty + j) * NF + fx + tx];
        __syncthreads();
        #pragma unroll
        for (int j2 = 0; j2 < 32; j2 += 8) {
            int fl = ty + j2;
            __nv_bfloat162 v = __floats2bfloat162_rn(t[2 * tx][fl], t[2 * tx + 1][fl]);
            *(__nv_bfloat162*)&g_WencT[(size_t)(fx + fl) * DM + dy + 2 * tx] = v;
        }
    } else if (b < BLK_TRE + BLK_TRD) {
        __shared__ float sm[32][257];
        int f0 = (b - BLK_TRE) * 32;
        #pragma unroll
        for (int cblk = 0; cblk < 8; cblk++)
            #pragma unroll
            for (int j = 0; j < 32; j += 8)
                sm[ty + j][cblk * 32 + tx] = Wdec[(size_t)(f0 + ty + j) * DM + cblk * 32 + tx];
        __syncthreads();
        #pragma unroll
        for (int r4 = 0; r4 < 4; r4++) {
            int r = ty * 4 + r4;
            float s = 0.f;
            #pragma unroll
            for (int q = 0; q < 8; q++) { float v = sm[r][q * 32 + tx]; s += v * v; }
            #pragma unroll
            for (int o = 16; o > 0; o >>= 1) s += __shfl_down_sync(0xffffffffu, s, o);
            if (tx == 0) g_wdn10[f0 + r] = 10.0f * sqrtf(s);
        }
        if (threadIdx.x < 32) g_cwseg[f0 + threadIdx.x] = g_cw[seg[f0 + threadIdx.x]];
        #pragma unroll
        for (int cblk = 0; cblk < 8; cblk++)
            #pragma unroll
            for (int j = 0; j < 32; j += 8)
                g_WdecT[(size_t)(cblk * 32 + ty + j) * NF + f0 + tx] =
                    __float2bfloat16(sm[tx][cblk * 32 + ty + j]);
    } else if (b < BLK_TRE + BLK_TRD + BLK_XN) {
        int i = (b - BLK_TRE - BLK_TRD) * 256 + threadIdx.x;
        float v = x[i] * g_scale;
        g_xn32[i] = v;
        g_xn[i] = __float2bfloat16(v);
    } else {
        __shared__ int bpos[16];
        __shared__ int bcnt;
        int tid = threadIdx.x;
        if (tid == 0) bcnt = 0;
        if (tid < KB) g_errsum[tid] = 0.f;
        __syncthreads();
        for (int f = tid + 1; f < NF; f += blockDim.x) {
            if (seg[f] != seg[f - 1]) {
                int i = atomicAdd(&bcnt, 1);
                if (i < 16) bpos[i] = f;
            }
        }
        __syncthreads();
        if (tid == 0) {
            int n = bcnt < 16 ? bcnt : 16;
            for (int i = 1; i < n; i++) {
                int v = bpos[i], j = i - 1;
                while (j >= 0 && bpos[j] > v) { bpos[j + 1] = bpos[j]; j--; }
                bpos[j + 1] = v;
            }
            int cur = 0, bi = 0, ni = 0;
            while (cur < NF && ni < MAX_ITEMS) {
                int nxt = ((cur / CHUNK) + 1) * CHUNK;
                while (bi < n && bpos[bi] <= cur) bi++;
                if (bi < n && bpos[bi] < nxt) nxt = bpos[bi];
                g_items[ni * 4 + 0] = cur;
                g_items[ni * 4 + 1] = nxt - cur;
                g_items[ni * 4 + 2] = seg[cur];
                g_items[ni * 4 + 3] = 0;
                ni++; cur = nxt;
            }
            for (int i = 0; i < ni; i++)
                g_items[i * 4 + 3] = (i == ni - 1) || (g_items[(i + 1) * 4 + 2] != g_items[i * 4 + 2]);
            for (int i = ni; i < MAX_ITEMS; i++) g_items[i * 4 + 1] = 0;
            for (int i = 0; i < MAX_ITEMS; i++) g_order[i] = i;
            for (int i = 1; i < MAX_ITEMS; i++) {
                int oi = g_order[i], li = g_items[oi * 4 + 1], j = i - 1;
                while (j >= 0 && g_items[g_order[j] * 4 + 1] < li) {
                    g_order[j + 1] = g_order[j]; j--;
                }
                g_order[j + 1] = oi;
            }
        }
    }
}

// ---------------- encode ----------------
#define ENC_SMEM (110592 + 1536)
#define DEC_SMEM 110592

__device__ __forceinline__ void enc_issue(uint32_t Ab, uint32_t Bb, int tid,
                                          int m0, int n0, int k0) {
    #pragma unroll
    for (int i = 0; i < 4; i++) {
        int slot = tid + i * 256, row = slot >> 3, c4 = slot & 7;
        uint32_t off = (uint32_t)(row * 144 + c4 * 16);
        cp16(Ab + off, &g_xn[(m0 + row) * DM + k0 + c4 * 8]);
        cp16(Bb + off, &g_WencT[(size_t)(n0 + row) * DM + k0 + c4 * 8]);
    }
    CP_COMMIT();
}

__global__ void __launch_bounds__(256, 2) k_encode(const float* __restrict__ benc) {
    extern __shared__ char smc[];
    uint32_t sb = (uint32_t)__cvta_generic_to_shared(smc);
    float* sArr = (float*)(smc + 110592);

    int tid = threadIdx.x, wid = tid >> 5, lane = tid & 31;
    int grp = lane >> 2, qid = lane & 3;
    int m0 = blockIdx.x * 128, n0 = blockIdx.y * 128;
    int rm = (wid & 3) * 32, rn = (wid >> 2) * 64;

    uint32_t aOff[2], bOff[4];
    #pragma unroll
    for (int mi = 0; mi < 2; mi++) {
        int row = rm + mi * 16 + (lane & 7) + ((lane >> 3) & 1) * 8;
        aOff[mi] = (uint32_t)(row * 144 + (lane >> 4) * 16);
    }
    #pragma unroll
    for (int nj = 0; nj < 4; nj++) {
        int row = rn + nj * 16 + (lane & 7) + (lane >> 4) * 8;
        bOff[nj] = (uint32_t)(row * 144 + ((lane >> 3) & 1) * 16);
    }

    enc_issue(sb, sb + 18432, tid, m0, n0, 0);
    enc_issue(sb + STG, sb + STG + 18432, tid, m0, n0, 64);

    if (tid < 128) {
        sArr[tid]       = benc[n0 + tid];
        sArr[128 + tid] = g_wdn10[n0 + tid];
        sArr[256 + tid] = g_cwseg[n0 + tid];
    }

    float c[2][8][4];
    #pragma unroll
    for (int i = 0; i < 2; i++)
        #pragma unroll
        for (int j = 0; j < 8; j++)
            #pragma unroll
            for (int q = 0; q < 4; q++) c[i][j][q] = 0.f;

    #pragma unroll
    for (int s = 0; s < 4; s++) {
        CP_WAIT1();
        __syncthreads();
        int nx = s + 2;
        if (nx < 4) {
            uint32_t base = sb + (uint32_t)(nx % 3) * STG;
            enc_issue(base, base + 18432, tid, m0, n0, nx * 64);
        } else CP_COMMIT();
        uint32_t cb = sb + (uint32_t)(s % 3) * STG;
        compute_chunk(cb, cb + 18432, aOff, bOff, c);
    }

    __syncthreads();
    __nv_bfloat16* sAct = (__nv_bfloat16*)(smc + STG);
    float l1loc = 0.f;
    int l0loc = 0;
    #pragma unroll
    for (int ni = 0; ni < 8; ni++) {
        int nl = rn + ni * 8 + qid * 2;
        float be0 = sArr[nl], be1 = sArr[nl + 1];
        float wd0 = sArr[128 + nl], wd1 = sArr[128 + nl + 1];
        float cw0 = sArr[256 + nl], cw1 = sArr[256 + nl + 1];
        float p0 = 1.f, p1 = 1.f;
        #pragma unroll
        for (int mi = 0; mi < 2; mi++) {
            int mr = rm + mi * 16 + grp;
            #pragma unroll
            for (int h = 0; h < 2; h++) {
                float a0 = fmaxf(c[mi][ni][h * 2 + 0] + be0, 0.f);
                float a1 = fmaxf(c[mi][ni][h * 2 + 1] + be1, 0.f);
                p0 *= fmaf(a0, wd0, 1.f);
                p1 *= fmaf(a1, wd1, 1.f);
                l0loc += (a0 > 0.f) + (a1 > 0.f);
                *(__nv_bfloat162*)&sAct[(mr + h * 8) * AP + nl] =
                    __floats2bfloat162_rn(a0, a1);
            }
        }
        l1loc += __logf(p0) * cw0 + __logf(p1) * cw1;
    }
    __syncthreads();
    #pragma unroll
    for (int it = 0; it < 8; it++) {
        int row = it * 16 + (tid >> 4);
        int col = (tid & 15) * 8;
        float4 v = *(float4*)&sAct[row * AP + col];
        *(float4*)&g_acts[(size_t)(m0 + row) * NF + n0 + col] = v;
    }
    float l0f = (float)l0loc;
    #pragma unroll
    for (int o = 16; o > 0; o >>= 1) {
        l1loc += __shfl_down_sync(0xffffffffu, l1loc, o);
        l0f   += __shfl_down_sync(0xffffffffu, l0f, o);
    }
    if (lane == 0) { atomicAdd(&g_l1sum, l1loc); atomicAdd(&g_l0sum, l0f); }
}

// ---------------- decode ----------------
__device__ __forceinline__ void dec_issue(uint32_t Ab, uint32_t Bb,
                                          __nv_bfloat16* Af, __nv_bfloat16* Bf,
                                          int tid, int m0, int d0,
                                          int fa, int lo, int hi, int k0) {
    int lo8 = lo ? 8 : 0;
    #pragma unroll
    for (int i = 0; i < 4; i++) {
        int slot = tid + i * 256, row = slot >> 3, c4 = slot & 7;
        int kb = k0 + c4 * 8;
        uint32_t off = (uint32_t)(row * 144 + c4 * 16);
        if (kb >= lo8 && kb + 7 < hi) {
            cp16(Ab + off, &g_acts[(size_t)(m0 + row) * NF + fa + kb]);
            cp16(Bb + off, &g_WdecT[(size_t)(d0 + row) * NF + fa + kb]);
        } else {
            #pragma unroll
            for (int e = 0; e < 8; e++) {
                int k = kb + e;
                bool v = (k >= lo) && (k < hi);
                __nv_bfloat16 av = v ? g_acts[(size_t)(m0 + row) * NF + fa + k] : __nv_bfloat16(0.f);
                __nv_bfloat16 bv = v ? g_WdecT[(size_t)(d0 + row) * NF + fa + k] : __nv_bfloat16(0.f);
                Af[row * 72 + c4 * 8 + e] = av;
                Bf[row * 72 + c4 * 8 + e] = bv;
            }
        }
    }
    CP_COMMIT();
}

__global__ void __launch_bounds__(256, 2) k_decode() {
    int item = g_order[blockIdx.z];
    int fs = g_items[item * 4 + 0], len = g_items[item * 4 + 1];
    if (len == 0) return;
    int fa = fs & ~7;
    int fe = fs + len;
    int lo = fs - fa, hi = fe - fa;
    int ns = (hi + 63) >> 6;

    extern __shared__ char smc[];
    uint32_t sb = (uint32_t)__cvta_generic_to_shared(smc);

    int tid = threadIdx.x, wid = tid >> 5, lane = tid & 31;
    int grp = lane >> 2, qid = lane & 3;
    int m0 = blockIdx.y * 128, d0 = blockIdx.x * 128;
    int rm = (wid & 3) * 32, rn = (wid >> 2) * 64;

    uint32_t aOff[2], bOff[4];
    #pragma unroll
    for (int mi = 0; mi < 2; mi++) {
        int row = rm + mi * 16 + (lane & 7) + ((lane >> 3) & 1) * 8;
        aOff[mi] = (uint32_t)(row * 144 + (lane >> 4) * 16);
    }
    #pragma unroll
    for (int nj = 0; nj < 4; nj++) {
        int row = rn + nj * 16 + (lane & 7) + (lane >> 4) * 8;
        bOff[nj] = (uint32_t)(row * 144 + ((lane >> 3) & 1) * 16);
    }

    float c[2][8][4];
    #pragma unroll
    for (int i = 0; i < 2; i++)
        #pragma unroll
        for (int j = 0; j < 8; j++)
            #pragma unroll
            for (int q = 0; q < 4; q++) c[i][j][q] = 0.f;

    dec_issue(sb, sb + 18432, (__nv_bfloat16*)smc, (__nv_bfloat16*)(smc + 18432),
              tid, m0, d0, fa, lo, hi, 0);
    if (ns > 1)
        dec_issue(sb + STG, sb + STG + 18432, (__nv_bfloat16*)(smc + STG),
                  (__nv_bfloat16*)(smc + STG + 18432), tid, m0, d0, fa, lo, hi, 64);
    else CP_COMMIT();

    #pragma unroll 1
    for (int s = 0; s < ns; s++) {
        CP_WAIT1();
        __syncthreads();
        int nx = s + 2;
        if (nx < ns) {
            uint32_t boff = (uint32_t)(nx % 3) * STG;
            dec_issue(sb + boff, sb + boff + 18432, (__nv_bfloat16*)(smc + boff),
                      (__nv_bfloat16*)(smc + boff + 18432), tid, m0, d0, fa, lo, hi, nx * 64);
        } else CP_COMMIT();
        uint32_t cb = sb + (uint32_t)(s % 3) * STG;
        compute_chunk(cb, cb + 18432, aOff, bOff, c);
    }

    __syncthreads();
    __nv_bfloat16* sP = (__nv_bfloat16*)(smc + STG);
    #pragma unroll
    for (int mi = 0; mi < 2; mi++) {
        int mr = rm + mi * 16 + grp;
        #pragma unroll
        for (int ni = 0; ni < 8; ni++) {
            int col = rn + ni * 8 + qid * 2;
            *(__nv_bfloat162*)&sP[mr * AP + col] =
                __floats2bfloat162_rn(c[mi][ni][0], c[mi][ni][1]);
            *(__nv_bfloat162*)&sP[(mr + 8) * AP + col] =
                __floats2bfloat162_rn(c[mi][ni][2], c[mi][ni][3]);
        }
    }
    __syncthreads();
    __nv_bfloat16* pbase = &g_part[(size_t)item * BATCH * DM];
    #pragma unroll
    for (int it = 0; it < 8; it++) {
        int row = it * 16 + (tid >> 4);
        int col = (tid & 15) * 8;
        float4 v = *(float4*)&sP[row * AP + col];
        *(float4*)&pbase[(size_t)(m0 + row) * DM + d0 + col] = v;
    }
}

// ---------------- cumulative item sum + per-block squared error ----------------
// Boundaries are encountered in ascending block order and every block is
// non-empty, so the j-th last-in-block boundary IS block j. One barrier total.
__global__ void k_err(const float* __restrict__ bdec) {
    __shared__ float sm[KB][256];
    int b = blockIdx.x, d = threadIdx.x;
    float xnv = g_xn32[b * DM + d];
    float cum = bdec[d];
    int j = 0;
    #pragma unroll 1
    for (int i = 0; i < MAX_ITEMS; i++) {
        int len = g_items[i * 4 + 1];
        if (len == 0) break;
        cum += __bfloat162float(g_part[(size_t)i * BATCH * DM + (size_t)b * DM + d]);
        if (g_items[i * 4 + 3]) {
            float e = cum - xnv;
            sm[j][d] = e * e;
            j++;
        }
    }
    __syncthreads();
    int w = d >> 5, lane = d & 31;
    if (w < KB) {
        float s = 0.f;
        #pragma unroll
        for (int q = 0; q < 8; q++) s += sm[w][lane + q * 32];
        #pragma unroll
        for (int o = 16; o > 0; o >>= 1) s += __shfl_down_sync(0xffffffffu, s, o);
        if (lane == 0) atomicAdd(&g_errsum[w], s);
    }
}

__global__ void k_final(const float* __restrict__ w, const float* __restrict__ l1_scale,
                        float* __restrict__ out) {
    float mse = 0.0f;
    for (int k = 0; k < KB; k++) mse += (g_errsum[k] / (float)BATCH) * w[k];
    mse /= (float)KB;
    float l1 = g_l1sum / (float)BATCH;
    float avg_l0 = g_l0sum / (float)BATCH;
    float s = (avg_l0 < 100.0f) ? l1_scale[0] * (1.0f - 3e-4f)
                                : l1_scale[0] * (1.0f + 3e-4f);
    out[0] = mse + s * l1;
}

// ---------------- launch ----------------
extern "C" void kernel_launch(void* const* d_in, const int* in_sizes, int n_in,
                              void* d_out, int out_size) {
    const float* x    = (const float*)d_in[0];
    const float* Wenc = (const float*)d_in[1];
    const float* benc = (const float*)d_in[2];
    const float* Wdec = (const float*)d_in[3];
    const float* bdec = (const float*)d_in[4];
    const float* bw   = (const float*)d_in[5];
    const float* ravg = (const float*)d_in[6];
    const float* l1s  = (const float*)d_in[7];
    const int*   seg  = (const int*)d_in[8];
    float* out = (float*)d_out;

    cudaFuncSetAttribute(k_encode, cudaFuncAttributeMaxDynamicSharedMemorySize, ENC_SMEM);
    cudaFuncSetAttribute(k_decode, cudaFuncAttributeMaxDynamicSharedMemorySize, DEC_SMEM);

    k_norms<<<BATCH / 8, 256>>>(x);
    k_prep<<<1, 256>>>(ravg, bw);
    k_all<<<ALL_BLOCKS, 256>>>(Wenc, Wdec, seg, x);
    k_encode<<<dim3(16, 256), 256, ENC_SMEM>>>(benc);
    k_decode<<<dim3(2, 16, MAX_ITEMS), 256, DEC_SMEM>>>();
    k_err<<<BATCH, 256>>>(bdec);
    k_final<<<1, 1>>>(bw, l1s, out);
}

// round 17
// speedup vs baseline: 1.0167x; 1.0167x over previous
#include <cuda_runtime.h>
#include <cuda_bf16.h>
#include <math.h>
#include <stdint.h>

#define BATCH 2048
#define DM    256
#define NF    32768
#define KB    8
#define CHUNK 1024
#define MAX_ITEMS 48
#define KPH   36
#define STG   36864u      // bytes per pipeline stage (A 18432 + B 18432)
#define AP    136         // epilogue staging row pitch (bf16 elements)

// ---------------- device globals ----------------
__device__ __nv_bfloat16 g_xn[BATCH * DM];
__device__ float         g_xn32[BATCH * DM];
__device__ __nv_bfloat16 g_acts[(size_t)BATCH * NF];
__device__ __nv_bfloat16 g_WencT[(size_t)NF * DM];
__device__ __nv_bfloat16 g_WdecT[(size_t)DM * NF];
__device__ __nv_bfloat16 g_part[(size_t)MAX_ITEMS * BATCH * DM];
__device__ float g_wdn10[NF];
__device__ float g_cwseg[NF];
__device__ float g_cw[KB];
__device__ float g_normpart[BATCH / 8];
__device__ float g_scale, g_l1sum, g_l0sum;
__device__ float g_errsum[KB];
__device__ int   g_items[4 * MAX_ITEMS];
__device__ int   g_order[MAX_ITEMS];

// ---------------- helpers ----------------
__device__ __forceinline__ void cp16(uint32_t dst, const void* src) {
    asm volatile("cp.async.cg.shared.global [%0], [%1], 16;" :: "r"(dst), "l"(src));
}
#define CP_COMMIT() asm volatile("cp.async.commit_group;" ::: "memory")
#define CP_WAIT1()  asm volatile("cp.async.wait_group 1;" ::: "memory")

__device__ __forceinline__ void mma16(float* c, const uint32_t* a, const uint32_t* b) {
    asm volatile(
        "mma.sync.aligned.m16n8k16.row.col.f32.bf16.bf16.f32 "
        "{%0,%1,%2,%3}, {%4,%5,%6,%7}, {%8,%9}, {%0,%1,%2,%3};"
        : "+f"(c[0]), "+f"(c[1]), "+f"(c[2]), "+f"(c[3])
        : "r"(a[0]), "r"(a[1]), "r"(a[2]), "r"(a[3]), "r"(b[0]), "r"(b[1]));
}

#define LDMX4(r0, r1, r2, r3, addr) \
    asm volatile("ldmatrix.sync.aligned.m8n8.x4.shared.b16 {%0,%1,%2,%3}, [%4];" \
        : "=r"(r0), "=r"(r1), "=r"(r2), "=r"(r3) : "r"(addr))

__device__ __forceinline__ void compute_chunk(uint32_t As, uint32_t Bs,
                                              const uint32_t aOff[2], const uint32_t bOff[4],
                                              float c[2][8][4]) {
    #pragma unroll
    for (int k4 = 0; k4 < 4; k4++) {
        uint32_t kb = (uint32_t)k4 * 32u;
        uint32_t a[2][4];
        LDMX4(a[0][0], a[0][1], a[0][2], a[0][3], As + aOff[0] + kb);
        LDMX4(a[1][0], a[1][1], a[1][2], a[1][3], As + aOff[1] + kb);
        uint32_t bb[4][4];
        #pragma unroll
        for (int nj = 0; nj < 4; nj++)
            LDMX4(bb[nj][0], bb[nj][1], bb[nj][2], bb[nj][3], Bs + bOff[nj] + kb);
        #pragma unroll
        for (int ni = 0; ni < 8; ni++) {
            uint32_t b2[2] = { bb[ni >> 1][(ni & 1) * 2], bb[ni >> 1][(ni & 1) * 2 + 1] };
            mma16(c[0][ni], a[0], b2);
            mma16(c[1][ni], a[1], b2);
        }
    }
}

// ---------------- small kernels ----------------
__global__ void k_norms(const float* __restrict__ x) {
    __shared__ float wsum[8];
    int warp = threadIdx.x >> 5, lane = threadIdx.x & 31;
    int row = blockIdx.x * 8 + warp;
    const float* p = x + row * DM + lane * 8;
    float4 v0 = *(const float4*)p;
    float4 v1 = *(const float4*)(p + 4);
    float s = v0.x*v0.x + v0.y*v0.y + v0.z*v0.z + v0.w*v0.w
            + v1.x*v1.x + v1.y*v1.y + v1.z*v1.z + v1.w*v1.w;
    #pragma unroll
    for (int o = 16; o > 0; o >>= 1) s += __shfl_down_sync(0xffffffffu, s, o);
    if (lane == 0) wsum[warp] = sqrtf(s);
    __syncthreads();
    if (threadIdx.x == 0) {
        float t = 0.f;
        #pragma unroll
        for (int i = 0; i < 8; i++) t += wsum[i];
        g_normpart[blockIdx.x] = t;
    }
}

__global__ void k_prep(const float* __restrict__ ravg, const float* __restrict__ w) {
    __shared__ float red[256];
    int tid = threadIdx.x;
    cudaGridDependencySynchronize();
    red[tid] = g_normpart[tid];
    __syncthreads();
    for (int s = 128; s > 0; s >>= 1) {
        if (tid < s) red[tid] += red[tid + s];
        __syncthreads();
    }
    if (tid == 0) {
        float mean = red[0] / (float)BATCH;
        float ra = 0.99f * ravg[0] + 0.01f * mean;
        g_scale = 16.0f / ra;
        float s = 0.0f;
        for (int j = KB - 1; j >= 0; j--) { s += w[j]; g_cw[j] = s / (float)KB; }
        g_l1sum = 0.f; g_l0sum = 0.f;
    }
}

#define BLK_TRE  4096
#define BLK_TRD  1024
#define BLK_XN   (BATCH * DM / 256)
#define ALL_BLOCKS (BLK_TRE + BLK_TRD + BLK_XN + 1)

__global__ void k_all(const float* __restrict__ Wenc, const float* __restrict__ Wdec,
                      const int* __restrict__ seg, const float* __restrict__ x) {
    int b = blockIdx.x;
    int tx = threadIdx.x & 31, ty = threadIdx.x >> 5;
    if (b < BLK_TRE) {
        // no predecessor dependency: runs concurrent with k_norms/k_prep under PDL
        __shared__ float t[64][33];
        int fx = (b & 1023) * 32;
        int dy = (b >> 10) * 64;
        #pragma unroll
        for (int j = 0; j < 64; j += 8)
            t[ty + j][tx] = Wenc[(size_t)(dy + ty + j) * NF + fx + tx];
        __syncthreads();
        #pragma unroll
        for (int j2 = 0; j2 < 32; j2 += 8) {
            int fl = ty + j2;
            __nv_bfloat162 v = __floats2bfloat162_rn(t[2 * tx][fl], t[2 * tx + 1][fl]);
            *(__nv_bfloat162*)&g_WencT[(size_t)(fx + fl) * DM + dy + 2 * tx] = v;
        }
    } else if (b < BLK_TRE + BLK_TRD) {
        __shared__ float sm[32][257];
        int f0 = (b - BLK_TRE) * 32;
        #pragma unroll
        for (int cblk = 0; cblk < 8; cblk++)
            #pragma unroll
            for (int j = 0; j < 32; j += 8)
                sm[ty + j][cblk * 32 + tx] = Wdec[(size_t)(f0 + ty + j) * DM + cblk * 32 + tx];
        __syncthreads();
        #pragma unroll
        for (int r4 = 0; r4 < 4; r4++) {
            int r = ty * 4 + r4;
            float s = 0.f;
            #pragma unroll
            for (int q = 0; q < 8; q++) { float v = sm[r][q * 32 + tx]; s += v * v; }
            #pragma unroll
            for (int o = 16; o > 0; o >>= 1) s += __shfl_down_sync(0xffffffffu, s, o);
            if (tx == 0) g_wdn10[f0 + r] = 10.0f * sqrtf(s);
        }
        if (threadIdx.x < 32) {
            cudaGridDependencySynchronize();     // g_cw written by k_prep
            g_cwseg[f0 + threadIdx.x] = g_cw[seg[f0 + threadIdx.x]];
        }
        #pragma unroll
        for (int cblk = 0; cblk < 8; cblk++)
            #pragma unroll
            for (int j = 0; j < 32; j += 8)
                g_WdecT[(size_t)(cblk * 32 + ty + j) * NF + f0 + tx] =
                    __float2bfloat16(sm[tx][cblk * 32 + ty + j]);
    } else if (b < BLK_TRE + BLK_TRD + BLK_XN) {
        cudaGridDependencySynchronize();         // g_scale written by k_prep
        int i = (b - BLK_TRE - BLK_TRD) * 256 + threadIdx.x;
        float v = x[i] * g_scale;
        g_xn32[i] = v;
        g_xn[i] = __float2bfloat16(v);
    } else {
        __shared__ int bpos[16];
        __shared__ int bcnt;
        int tid = threadIdx.x;
        if (tid == 0) bcnt = 0;
        if (tid < KB) g_errsum[tid] = 0.f;
        __syncthreads();
        for (int f = tid + 1; f < NF; f += blockDim.x) {
            if (seg[f] != seg[f - 1]) {
                int i = atomicAdd(&bcnt, 1);
                if (i < 16) bpos[i] = f;
            }
        }
        __syncthreads();
        if (tid == 0) {
            int n = bcnt < 16 ? bcnt : 16;
            for (int i = 1; i < n; i++) {
                int v = bpos[i], j = i - 1;
                while (j >= 0 && bpos[j] > v) { bpos[j + 1] = bpos[j]; j--; }
                bpos[j + 1] = v;
            }
            int cur = 0, bi = 0, ni = 0;
            while (cur < NF && ni < MAX_ITEMS) {
                int nxt = ((cur / CHUNK) + 1) * CHUNK;
                while (bi < n && bpos[bi] <= cur) bi++;
                if (bi < n && bpos[bi] < nxt) nxt = bpos[bi];
                g_items[ni * 4 + 0] = cur;
                g_items[ni * 4 + 1] = nxt - cur;
                g_items[ni * 4 + 2] = seg[cur];
                g_items[ni * 4 + 3] = 0;
                ni++; cur = nxt;
            }
            for (int i = 0; i < ni; i++)
                g_items[i * 4 + 3] = (i == ni - 1) || (g_items[(i + 1) * 4 + 2] != g_items[i * 4 + 2]);
            for (int i = ni; i < MAX_ITEMS; i++) g_items[i * 4 + 1] = 0;
            for (int i = 0; i < MAX_ITEMS; i++) g_order[i] = i;
            for (int i = 1; i < MAX_ITEMS; i++) {
                int oi = g_order[i], li = g_items[oi * 4 + 1], j = i - 1;
                while (j >= 0 && g_items[g_order[j] * 4 + 1] < li) {
                    g_order[j + 1] = g_order[j]; j--;
                }
                g_order[j + 1] = oi;
            }
        }
    }
}

// ---------------- encode ----------------
#define ENC_SMEM (110592 + 1536)
#define DEC_SMEM 110592

__device__ __forceinline__ void enc_issue(uint32_t Ab, uint32_t Bb, int tid,
                                          int m0, int n0, int k0) {
    #pragma unroll
    for (int i = 0; i < 4; i++) {
        int slot = tid + i * 256, row = slot >> 3, c4 = slot & 7;
        uint32_t off = (uint32_t)(row * 144 + c4 * 16);
        cp16(Ab + off, &g_xn[(m0 + row) * DM + k0 + c4 * 8]);
        cp16(Bb + off, &g_WencT[(size_t)(n0 + row) * DM + k0 + c4 * 8]);
    }
    CP_COMMIT();
}

__global__ void __launch_bounds__(256, 2) k_encode(const float* __restrict__ benc) {
    extern __shared__ char smc[];
    uint32_t sb = (uint32_t)__cvta_generic_to_shared(smc);
    float* sArr = (float*)(smc + 110592);

    int tid = threadIdx.x, wid = tid >> 5, lane = tid & 31;
    int grp = lane >> 2, qid = lane & 3;
    int m0 = blockIdx.x * 128, n0 = blockIdx.y * 128;
    int rm = (wid & 3) * 32, rn = (wid >> 2) * 64;

    uint32_t aOff[2], bOff[4];
    #pragma unroll
    for (int mi = 0; mi < 2; mi++) {
        int row = rm + mi * 16 + (lane & 7) + ((lane >> 3) & 1) * 8;
        aOff[mi] = (uint32_t)(row * 144 + (lane >> 4) * 16);
    }
    #pragma unroll
    for (int nj = 0; nj < 4; nj++) {
        int row = rn + nj * 16 + (lane & 7) + (lane >> 4) * 8;
        bOff[nj] = (uint32_t)(row * 144 + ((lane >> 3) & 1) * 16);
    }

    cudaGridDependencySynchronize();             // wait for k_all outputs

    enc_issue(sb, sb + 18432, tid, m0, n0, 0);
    enc_issue(sb + STG, sb + STG + 18432, tid, m0, n0, 64);

    if (tid < 128) {
        sArr[tid]       = benc[n0 + tid];
        sArr[128 + tid] = g_wdn10[n0 + tid];
        sArr[256 + tid] = g_cwseg[n0 + tid];
    }

    float c[2][8][4];
    #pragma unroll
    for (int i = 0; i < 2; i++)
        #pragma unroll
        for (int j = 0; j < 8; j++)
            #pragma unroll
            for (int q = 0; q < 4; q++) c[i][j][q] = 0.f;

    #pragma unroll
    for (int s = 0; s < 4; s++) {
        CP_WAIT1();
        __syncthreads();
        int nx = s + 2;
        if (nx < 4) {
            uint32_t base = sb + (uint32_t)(nx % 3) * STG;
            enc_issue(base, base + 18432, tid, m0, n0, nx * 64);
        } else CP_COMMIT();
        uint32_t cb = sb + (uint32_t)(s % 3) * STG;
        compute_chunk(cb, cb + 18432, aOff, bOff, c);
    }

    __syncthreads();
    __nv_bfloat16* sAct = (__nv_bfloat16*)(smc + STG);
    float l1loc = 0.f;
    int l0loc = 0;
    #pragma unroll
    for (int ni = 0; ni < 8; ni++) {
        int nl = rn + ni * 8 + qid * 2;
        float be0 = sArr[nl], be1 = sArr[nl + 1];
        float wd0 = sArr[128 + nl], wd1 = sArr[128 + nl + 1];
        float cw0 = sArr[256 + nl], cw1 = sArr[256 + nl + 1];
        float p0 = 1.f, p1 = 1.f;
        #pragma unroll
        for (int mi = 0; mi < 2; mi++) {
            int mr = rm + mi * 16 + grp;
            #pragma unroll
            for (int h = 0; h < 2; h++) {
                float a0 = fmaxf(c[mi][ni][h * 2 + 0] + be0, 0.f);
                float a1 = fmaxf(c[mi][ni][h * 2 + 1] + be1, 0.f);
                p0 *= fmaf(a0, wd0, 1.f);
                p1 *= fmaf(a1, wd1, 1.f);
                l0loc += (a0 > 0.f) + (a1 > 0.f);
                *(__nv_bfloat162*)&sAct[(mr + h * 8) * AP + nl] =
                    __floats2bfloat162_rn(a0, a1);
            }
        }
        l1loc += __logf(p0) * cw0 + __logf(p1) * cw1;
    }
    __syncthreads();
    #pragma unroll
    for (int it = 0; it < 8; it++) {
        int row = it * 16 + (tid >> 4);
        int col = (tid & 15) * 8;
        float4 v = *(float4*)&sAct[row * AP + col];
        *(float4*)&g_acts[(size_t)(m0 + row) * NF + n0 + col] = v;
    }
    float l0f = (float)l0loc;
    #pragma unroll
    for (int o = 16; o > 0; o >>= 1) {
        l1loc += __shfl_down_sync(0xffffffffu, l1loc, o);
        l0f   += __shfl_down_sync(0xffffffffu, l0f, o);
    }
    if (lane == 0) { atomicAdd(&g_l1sum, l1loc); atomicAdd(&g_l0sum, l0f); }
}

// ---------------- decode ----------------
__device__ __forceinline__ void dec_issue(uint32_t Ab, uint32_t Bb,
                                          __nv_bfloat16* Af, __nv_bfloat16* Bf,
                                          int tid, int m0, int d0,
                                          int fa, int lo, int hi, int k0) {
    int lo8 = lo ? 8 : 0;
    #pragma unroll
    for (int i = 0; i < 4; i++) {
        int slot = tid + i * 256, row = slot >> 3, c4 = slot & 7;
        int kb = k0 + c4 * 8;
        uint32_t off = (uint32_t)(row * 144 + c4 * 16);
        if (kb >= lo8 && kb + 7 < hi) {
            cp16(Ab + off, &g_acts[(size_t)(m0 + row) * NF + fa + kb]);
            cp16(Bb + off, &g_WdecT[(size_t)(d0 + row) * NF + fa + kb]);
        } else {
            #pragma unroll
            for (int e = 0; e < 8; e++) {
                int k = kb + e;
                bool v = (k >= lo) && (k < hi);
                __nv_bfloat16 av = v ? g_acts[(size_t)(m0 + row) * NF + fa + k] : __nv_bfloat16(0.f);
                __nv_bfloat16 bv = v ? g_WdecT[(size_t)(d0 + row) * NF + fa + k] : __nv_bfloat16(0.f);
                Af[row * 72 + c4 * 8 + e] = av;
                Bf[row * 72 + c4 * 8 + e] = bv;
            }
        }
    }
    CP_COMMIT();
}

__global__ void __launch_bounds__(256, 2) k_decode() {
    cudaGridDependencySynchronize();             // wait for k_encode acts
    int item = g_order[blockIdx.z];
    int fs = g_items[item * 4 + 0], len = g_items[item * 4 + 1];
    if (len == 0) return;
    int fa = fs & ~7;
    int fe = fs + len;
    int lo = fs - fa, hi = fe - fa;
    int ns = (hi + 63) >> 6;

    extern __shared__ char smc[];
    uint32_t sb = (uint32_t)__cvta_generic_to_shared(smc);

    int tid = threadIdx.x, wid = tid >> 5, lane = tid & 31;
    int grp = lane >> 2, qid = lane & 3;
    int m0 = blockIdx.y * 128, d0 = blockIdx.x * 128;
    int rm = (wid & 3) * 32, rn = (wid >> 2) * 64;

    uint32_t aOff[2], bOff[4];
    #pragma unroll
    for (int mi = 0; mi < 2; mi++) {
        int row = rm + mi * 16 + (lane & 7) + ((lane >> 3) & 1) * 8;
        aOff[mi] = (uint32_t)(row * 144 + (lane >> 4) * 16);
    }
    #pragma unroll
    for (int nj = 0; nj < 4; nj++) {
        int row = rn + nj * 16 + (lane & 7) + (lane >> 4) * 8;
        bOff[nj] = (uint32_t)(row * 144 + ((lane >> 3) & 1) * 16);
    }

    float c[2][8][4];
    #pragma unroll
    for (int i = 0; i < 2; i++)
        #pragma unroll
        for (int j = 0; j < 8; j++)
            #pragma unroll
            for (int q = 0; q < 4; q++) c[i][j][q] = 0.f;

    dec_issue(sb, sb + 18432, (__nv_bfloat16*)smc, (__nv_bfloat16*)(smc + 18432),
              tid, m0, d0, fa, lo, hi, 0);
    if (ns > 1)
        dec_issue(sb + STG, sb + STG + 18432, (__nv_bfloat16*)(smc + STG),
                  (__nv_bfloat16*)(smc + STG + 18432), tid, m0, d0, fa, lo, hi, 64);
    else CP_COMMIT();

    #pragma unroll 1
    for (int s = 0; s < ns; s++) {
        CP_WAIT1();
        __syncthreads();
        int nx = s + 2;
        if (nx < ns) {
            uint32_t boff = (uint32_t)(nx % 3) * STG;
            dec_issue(sb + boff, sb + boff + 18432, (__nv_bfloat16*)(smc + boff),
                      (__nv_bfloat16*)(smc + boff + 18432), tid, m0, d0, fa, lo, hi, nx * 64);
        } else CP_COMMIT();
        uint32_t cb = sb + (uint32_t)(s % 3) * STG;
        compute_chunk(cb, cb + 18432, aOff, bOff, c);
    }

    __syncthreads();
    __nv_bfloat16* sP = (__nv_bfloat16*)(smc + STG);
    #pragma unroll
    for (int mi = 0; mi < 2; mi++) {
        int mr = rm + mi * 16 + grp;
        #pragma unroll
        for (int ni = 0; ni < 8; ni++) {
            int col = rn + ni * 8 + qid * 2;
            *(__nv_bfloat162*)&sP[mr * AP + col] =
                __floats2bfloat162_rn(c[mi][ni][0], c[mi][ni][1]);
            *(__nv_bfloat162*)&sP[(mr + 8) * AP + col] =
                __floats2bfloat162_rn(c[mi][ni][2], c[mi][ni][3]);
        }
    }
    __syncthreads();
    __nv_bfloat16* pbase = &g_part[(size_t)item * BATCH * DM];
    #pragma unroll
    for (int it = 0; it < 8; it++) {
        int row = it * 16 + (tid >> 4);
        int col = (tid & 15) * 8;
        float4 v = *(float4*)&sP[row * AP + col];
        *(float4*)&pbase[(size_t)(m0 + row) * DM + d0 + col] = v;
    }
}

// ---------------- cumulative item sum + per-block squared error ----------------
__global__ void k_err(const float* __restrict__ bdec) {
    int b = blockIdx.x, d = threadIdx.x;
    __shared__ float red[256];
    cudaGridDependencySynchronize();             // wait for k_decode partials
    float xnv = g_xn32[b * DM + d];
    float cum = bdec[d];
    for (int i = 0; i < MAX_ITEMS; i++) {
        int len = g_items[i * 4 + 1];
        if (len == 0) break;
        cum += __bfloat162float(g_part[(size_t)i * BATCH * DM + (size_t)b * DM + d]);
        if (g_items[i * 4 + 3]) {
            float e = cum - xnv;
            red[d] = e * e;
            __syncthreads();
            for (int s = 128; s > 0; s >>= 1) {
                if (d < s) red[d] += red[d + s];
                __syncthreads();
            }
            if (d == 0) atomicAdd(&g_errsum[g_items[i * 4 + 2]], red[0]);
            __syncthreads();
        }
    }
}

__global__ void k_final(const float* __restrict__ w, const float* __restrict__ l1_scale,
                        float* __restrict__ out) {
    cudaGridDependencySynchronize();
    float mse = 0.0f;
    for (int k = 0; k < KB; k++) mse += (g_errsum[k] / (float)BATCH) * w[k];
    mse /= (float)KB;
    float l1 = g_l1sum / (float)BATCH;
    float avg_l0 = g_l0sum / (float)BATCH;
    float s = (avg_l0 < 100.0f) ? l1_scale[0] * (1.0f - 3e-4f)
                                : l1_scale[0] * (1.0f + 3e-4f);
    out[0] = mse + s * l1;
}

// ---------------- launch ----------------
template <typename K, typename... Args>
static void launch_pdl(K kern, dim3 grid, dim3 block, size_t smem, Args... args) {
    cudaLaunchConfig_t cfg = {};
    cfg.gridDim = grid;
    cfg.blockDim = block;
    cfg.dynamicSmemBytes = smem;
    cfg.stream = 0;
    cudaLaunchAttribute attr[1];
    attr[0].id = cudaLaunchAttributeProgrammaticStreamSerialization;
    attr[0].val.programmaticStreamSerializationAllowed = 1;
    cfg.attrs = attr;
    cfg.numAttrs = 1;
    cudaLaunchKernelEx(&cfg, kern, args...);
}

extern "C" void kernel_launch(void* const* d_in, const int* in_sizes, int n_in,
                              void* d_out, int out_size) {
    const float* x    = (const float*)d_in[0];
    const float* Wenc = (const float*)d_in[1];
    const float* benc = (const float*)d_in[2];
    const float* Wdec = (const float*)d_in[3];
    const float* bdec = (const float*)d_in[4];
    const float* bw   = (const float*)d_in[5];
    const float* ravg = (const float*)d_in[6];
    const float* l1s  = (const float*)d_in[7];
    const int*   seg  = (const int*)d_in[8];
    float* out = (float*)d_out;

    cudaFuncSetAttribute(k_encode, cudaFuncAttributeMaxDynamicSharedMemorySize, ENC_SMEM);
    cudaFuncSetAttribute(k_decode, cudaFuncAttributeMaxDynamicSharedMemorySize, DEC_SMEM);

    k_norms<<<BATCH / 8, 256>>>(x);
    launch_pdl(k_prep, dim3(1), dim3(256), 0, ravg, bw);
    launch_pdl(k_all, dim3(ALL_BLOCKS), dim3(256), 0, Wenc, Wdec, seg, x);
    launch_pdl(k_encode, dim3(16, 256), dim3(256), (size_t)ENC_SMEM, benc);
    launch_pdl(k_decode, dim3(2, 16, MAX_ITEMS), dim3(256), (size_t)DEC_SMEM);
    launch_pdl(k_err, dim3(BATCH), dim3(256), 0, bdec);
    launch_pdl(k_final, dim3(1), dim3(1), 0, bw, l1s, out);
}